// round 17
// baseline (speedup 1.0000x reference)
#include <cuda_runtime.h>
#include <cuda_fp16.h>
#include <math.h>
#include <stdint.h>

// Problem constants
#define NROWS 32768   // B*H*W
#define DDIM  64
#define MCODE 1024
#define HWSZ  1024
#define ZQ_ELEMS 2097152

// Static device scratch
__device__ float g_key[2 * NROWS];       // per code-half: min key (y2 - 2*dot)
__device__ float g_kidx[2 * NROWS];      // per code-half: argmin index (as float)
__device__ float g_y2[MCODE];
__device__ unsigned long long g_lacc = 0ull;  // fixed-point sum of s^2 (scale 2^22)
__device__ int   g_ctr = 0;              // zq completion counter (self-resetting)
__device__ int   g_pk = 0;               // pack-done counter (self-resetting)
// Codebook packed fp16 hi/lo fragment order:
// [chunk(16)][s(4)][ci(64)][tt(4)] uint4 = { h2(k0,k0+1), h2(k0+8,k0+9),
//                                            l2(k0,k0+1), l2(k0+8,k0+9) },
// k0 = 16*s + 2*tt.  16KB per 64-code chunk.
__device__ uint4 g_bpack[16 * 1024];

// ---------------------------------------------------------------------------
// helpers
// ---------------------------------------------------------------------------
__device__ __forceinline__ uint32_t h2u(__half2 h) {
    return *reinterpret_cast<uint32_t*>(&h);
}
__device__ __forceinline__ void split2(float a, float b, uint32_t& hi, uint32_t& lo) {
    __half2 h = __floats2half2_rn(a, b);
    float2 f = __half22float2(h);
    __half2 l = __floats2half2_rn(a - f.x, b - f.y);
    hi = h2u(h); lo = h2u(l);
}
__device__ __forceinline__ uint32_t smem_u32(const void* p) {
    uint32_t a;
    asm("{ .reg .u64 t; cvta.to.shared.u64 t, %1; cvt.u32.u64 %0, t; }"
        : "=r"(a) : "l"(p));
    return a;
}
__device__ __forceinline__ void bulk_g2s(uint32_t dst, const void* src,
                                         uint32_t bytes, uint32_t mbar) {
    asm volatile(
        "cp.async.bulk.shared::cta.global.mbarrier::complete_tx::bytes [%0], [%1], %2, [%3];"
        :: "r"(dst), "l"(src), "r"(bytes), "r"(mbar) : "memory");
}
__device__ __forceinline__ void mbar_init(uint32_t mbar, uint32_t cnt) {
    asm volatile("mbarrier.init.shared.b64 [%0], %1;" :: "r"(mbar), "r"(cnt) : "memory");
}
__device__ __forceinline__ void mbar_expect_tx(uint32_t mbar, uint32_t bytes) {
    asm volatile("mbarrier.arrive.expect_tx.shared.b64 _, [%0], %1;"
                 :: "r"(mbar), "r"(bytes) : "memory");
}
__device__ __forceinline__ void mbar_wait(uint32_t mbar, uint32_t parity) {
    uint32_t done;
    asm volatile(
        "{\n\t.reg .pred p;\n\t"
        "mbarrier.try_wait.parity.acquire.cta.shared::cta.b64 p, [%1], %2;\n\t"
        "selp.b32 %0, 1, 0, p;\n\t}"
        : "=r"(done) : "r"(mbar), "r"(parity) : "memory");
    while (!done) {
        asm volatile(
            "{\n\t.reg .pred p;\n\t"
            "mbarrier.try_wait.parity.acquire.cta.shared::cta.b64 p, [%1], %2, 0x989680;\n\t"
            "selp.b32 %0, 1, 0, p;\n\t}"
            : "=r"(done) : "r"(mbar), "r"(parity) : "memory");
    }
}
// D(16x8) += A(16x16) * B(16x8), fp16 inputs, fp32 accum
__device__ __forceinline__ void mma16n8k16(float* c, uint32_t a0, uint32_t a1,
                                           uint32_t a2, uint32_t a3,
                                           uint32_t b0, uint32_t b1) {
    asm volatile(
        "mma.sync.aligned.m16n8k16.row.col.f32.f16.f16.f32 "
        "{%0,%1,%2,%3}, {%4,%5,%6,%7}, {%8,%9}, {%0,%1,%2,%3};"
        : "+f"(c[0]), "+f"(c[1]), "+f"(c[2]), "+f"(c[3])
        : "r"(a0), "r"(a1), "r"(a2), "r"(a3), "r"(b0), "r"(b1));
}

// ---------------------------------------------------------------------------
// Kernel 1: 3xFP16 m16n8k16 distance GEMM + fused argmin + COOPERATIVE
// codebook packing prologue (CTAs 0..31 pack; all 148 CTAs spin on g_pk,
// overlapped with A-prep; deadlock-free since grid 148 = one full wave).
// Grid 148 = 74 uneven row blocks (12x416 + 62x448) x 2 code halves.
// ---------------------------------------------------------------------------
#define SM_MB   0
#define SM_Y2   128
#define SM_A    2176
#define SM_B    133248                   // SM_A + 4*512*4*16 = 131072
#define GEMM_SMEM (133248 + 2 * 16384)   // 166016

__global__ __launch_bounds__(512, 1)
void gemm_argmin_kernel(const float* __restrict__ z, const float* __restrict__ cb) {
    extern __shared__ char sm[];
    uint32_t sb = smem_u32(sm);
    uint4* A4 = (uint4*)(sm + SM_A);
    const float* y2s = (const float*)(sm + SM_Y2);
    int tid = threadIdx.x;
    int wid = tid >> 5, lane = tid & 31;
    int g = lane >> 2, tt = lane & 3;
    int half = blockIdx.x & 1;
    int bi = blockIdx.x >> 1;            // 0..73
    int r0, rows;
    if (bi < 12) { r0 = bi * 416;               rows = 416; }
    else         { r0 = 4992 + (bi - 12) * 448; rows = 448; }
    int w32 = wid * 32;
    bool active = (w32 < rows);
    const uint4* bsrc = g_bpack + half * 8 * 1024;

    if (tid == 0) {
        mbar_init(sb + SM_MB + 0, 1);
        mbar_init(sb + SM_MB + 8, 1);
    }

    // ---- cooperative pack: CTAs 0..31 each pack 512 units (1/thread) ----
    bool packer = (blockIdx.x < 32);
    if (packer) {
        int u = blockIdx.x * 512 + tid;      // 0..16383
        int c = u >> 4, s = (u >> 2) & 3, t4 = u & 3;
        int k0 = 16 * s + 2 * t4;
        float v0 = cb[c * DDIM + k0];
        float v1 = cb[c * DDIM + k0 + 1];
        float v8 = cb[c * DDIM + k0 + 8];
        float v9 = cb[c * DDIM + k0 + 9];
        uint32_t h01, l01, h89, l89;
        split2(v0, v1, h01, l01);
        split2(v8, v9, h89, l89);
        int chunk = c >> 6, ci = c & 63;
        g_bpack[chunk * 1024 + s * 256 + ci * 4 + t4] = make_uint4(h01, h89, l01, l89);
        float y = v0 * v0 + v1 * v1 + v8 * v8 + v9 * v9;
        y += __shfl_down_sync(0xffffffffu, y, 8, 16);
        y += __shfl_down_sync(0xffffffffu, y, 4, 16);
        y += __shfl_down_sync(0xffffffffu, y, 2, 16);
        y += __shfl_down_sync(0xffffffffu, y, 1, 16);
        if ((u & 15) == 0) g_y2[c] = y;
        __threadfence();                     // release pack stores (per-thread)
    }
    __syncthreads();                         // mbar init + pack stores done
    if (packer && tid == 0) atomicAdd(&g_pk, 1);

    // A prep: z -> fp16 hi/lo fragment uint4s (overlaps other CTAs' packing)
    {
        int roff = lane >> 2, tp = lane & 3;
        #pragma unroll
        for (int p = 0; p < 4; ++p) {
            int r = p * 128 + wid * 8 + roff;
            if (r < rows) {
                int n = r0 + r;
                const float* zp = z + (size_t)(n >> 10) * 65536 + (n & 1023);
                #pragma unroll
                for (int s = 0; s < 4; ++s) {
                    int k0 = 16 * s + 2 * tp;
                    float v0 = zp[k0 * 1024];
                    float v1 = zp[(k0 + 1) * 1024];
                    float v8 = zp[(k0 + 8) * 1024];
                    float v9 = zp[(k0 + 9) * 1024];
                    uint32_t h01, l01, h89, l89;
                    split2(v0, v1, h01, l01);
                    split2(v8, v9, h89, l89);
                    A4[(s * 512 + r) * 4 + tp] = make_uint4(h01, h89, l01, l89);
                }
            }
        }
    }

    // wait for all packers (acquire), then start the B pipeline
    if (tid == 0) {
        int done;
        do {
            asm volatile("ld.acquire.gpu.s32 %0, [%1];" : "=r"(done) : "l"(&g_pk));
        } while (done < 32);
    }
    __syncthreads();
    if (tid == 0) {
        mbar_expect_tx(sb + SM_MB + 0, 16384);
        bulk_g2s(sb + SM_B, bsrc, 16384, sb + SM_MB + 0);
        mbar_expect_tx(sb + SM_MB + 8, 16384);
        bulk_g2s(sb + SM_B + 16384, bsrc + 1024, 16384, sb + SM_MB + 8);
    }
    for (int i = tid; i < 512; i += 512)
        ((float*)(sm + SM_Y2))[i] = g_y2[half * 512 + i];
    __syncthreads();

    float best[4];
    int   bidx[4];
    #pragma unroll
    for (int i = 0; i < 4; ++i) { best[i] = 3.4028235e38f; bidx[i] = 0; }

    for (int ch = 0; ch < 8; ++ch) {
        int buf = ch & 1;
        mbar_wait(sb + SM_MB + buf * 8, (ch >> 1) & 1);

        if (active) {
            const uint4* Bb = (const uint4*)(sm + SM_B + buf * 16384);

            float acc[2][8][4];
            #pragma unroll
            for (int m = 0; m < 2; ++m)
                #pragma unroll
                for (int j = 0; j < 8; ++j)
                    #pragma unroll
                    for (int e = 0; e < 4; ++e) acc[m][j][e] = 0.f;

            #pragma unroll
            for (int s = 0; s < 4; ++s) {
                uint4 ra = A4[(s * 512 + w32 + g) * 4 + tt];       // row g
                uint4 rb = A4[(s * 512 + w32 + 8 + g) * 4 + tt];   // row g+8
                uint4 rc = A4[(s * 512 + w32 + 16 + g) * 4 + tt];  // row g+16
                uint4 rd = A4[(s * 512 + w32 + 24 + g) * 4 + tt];  // row g+24
                #pragma unroll
                for (int j = 0; j < 8; ++j) {
                    uint4 bq = Bb[s * 256 + (j * 8 + g) * 4 + tt]; // {bh01,bh89,bl01,bl89}
                    mma16n8k16(acc[0][j], ra.x, rb.x, ra.y, rb.y, bq.x, bq.y); // hi*hi
                    mma16n8k16(acc[0][j], ra.x, rb.x, ra.y, rb.y, bq.z, bq.w); // hi*lo
                    mma16n8k16(acc[0][j], ra.z, rb.z, ra.w, rb.w, bq.x, bq.y); // lo*hi
                    mma16n8k16(acc[1][j], rc.x, rd.x, rc.y, rd.y, bq.x, bq.y);
                    mma16n8k16(acc[1][j], rc.x, rd.x, rc.y, rd.y, bq.z, bq.w);
                    mma16n8k16(acc[1][j], rc.z, rd.z, rc.w, rd.w, bq.x, bq.y);
                }
            }

            // epilogue: key = y2 - 2*dot, running argmin (first-occurrence ties)
            #pragma unroll
            for (int j = 0; j < 8; ++j) {
                int cl = ch * 64 + j * 8 + 2 * tt;
                float2 y = ((const float2*)y2s)[cl >> 1];
                #pragma unroll
                for (int m = 0; m < 2; ++m) {
                    float k0 = fmaf(acc[m][j][0], -2.0f, y.x);
                    float k1 = fmaf(acc[m][j][1], -2.0f, y.y);
                    float k2 = fmaf(acc[m][j][2], -2.0f, y.x);
                    float k3 = fmaf(acc[m][j][3], -2.0f, y.y);
                    if (k0 < best[m * 2 + 0]) { best[m * 2 + 0] = k0; bidx[m * 2 + 0] = cl; }
                    if (k1 < best[m * 2 + 0]) { best[m * 2 + 0] = k1; bidx[m * 2 + 0] = cl + 1; }
                    if (k2 < best[m * 2 + 1]) { best[m * 2 + 1] = k2; bidx[m * 2 + 1] = cl; }
                    if (k3 < best[m * 2 + 1]) { best[m * 2 + 1] = k3; bidx[m * 2 + 1] = cl + 1; }
                }
            }
        }

        __syncthreads();  // everyone done with buf before refill
        if (ch + 2 < 8 && tid == 0) {
            mbar_expect_tx(sb + SM_MB + buf * 8, 16384);
            bulk_g2s(sb + SM_B + buf * 16384, bsrc + (ch + 2) * 1024, 16384,
                     sb + SM_MB + buf * 8);
        }
    }

    // cross-lane (t-group) argmin reduce; lane with tt==0 owns the row
    if (active) {
        #pragma unroll
        for (int m = 0; m < 4; ++m) {
            float v = best[m];
            int id = bidx[m];
            #pragma unroll
            for (int d = 1; d < 4; d <<= 1) {
                float v2 = __shfl_xor_sync(0xffffffffu, v, d);
                int   i2 = __shfl_xor_sync(0xffffffffu, id, d);
                if (v2 < v || (v2 == v && i2 < id)) { v = v2; id = i2; }
            }
            if (tt == 0) {
                int row = r0 + w32 + (m >> 1) * 16 + (m & 1) * 8 + g;
                g_key[half * NROWS + row] = v;
                g_kidx[half * NROWS + row] = (float)(half * 512 + id);
            }
        }
    }
}

// ---------------------------------------------------------------------------
// Kernel 2: z_q, output transpose, ind merge + fixed-point loss (warp-shuffle
// reduction, single barrier). Last CTA finalizes + resets counters.
// ---------------------------------------------------------------------------
__global__ __launch_bounds__(256)
void zq_kernel(const float* __restrict__ z,
               const float* __restrict__ noise,
               float* __restrict__ out,
               float* __restrict__ out_ind,
               float* __restrict__ out_loss) {
    __shared__ float zt[64][33];     // z[b, d, hw0+w] tile
    __shared__ float zq[32 * 65];
    __shared__ float wred[8];
    int t = threadIdx.x;
    int c = blockIdx.x;
    int b = c >> 5;
    int p = c & 31;
    int r0 = b * 1024 + p * 32;

    int row = t >> 3;
    int seg = t & 7;
    int n = r0 + row;

    // hoisted independent loads (issue before the tile barrier)
    float4 n0 = *(const float4*)&noise[n * 64 + seg * 8];
    float4 n1 = *(const float4*)&noise[n * 64 + seg * 8 + 4];
    float k0 = g_key[n], k1 = g_key[NROWS + n];
    float i0 = g_kidx[n], i1 = g_kidx[NROWS + n];

    // load z tile: 64 d x 32 hw, coalesced over hw
    {
        const float* zb = z + (size_t)b * 65536 + p * 32;
        int w = t & 31, db = t >> 5;
        #pragma unroll
        for (int it = 0; it < 8; ++it) {
            int d = it * 8 + db;
            zt[d][w] = zb[d * 1024 + w];
        }
    }
    __syncthreads();

    float nv[8] = {n0.x, n0.y, n0.z, n0.w, n1.x, n1.y, n1.z, n1.w};
    float zv[8];
    #pragma unroll
    for (int i = 0; i < 8; ++i) zv[i] = zt[seg * 8 + i][row];

    float s = 0.f, xs = 0.f;
    #pragma unroll
    for (int i = 0; i < 8; ++i) { s += nv[i] * nv[i]; xs += zv[i] * zv[i]; }
    s += __shfl_down_sync(0xffffffffu, s, 4, 8);
    xs += __shfl_down_sync(0xffffffffu, xs, 4, 8);
    s += __shfl_down_sync(0xffffffffu, s, 2, 8);
    xs += __shfl_down_sync(0xffffffffu, xs, 2, 8);
    s += __shfl_down_sync(0xffffffffu, s, 1, 8);
    xs += __shfl_down_sync(0xffffffffu, xs, 1, 8);
    float norm2 = __shfl_sync(0xffffffffu, s, 0, 8);
    float x2 = __shfl_sync(0xffffffffu, xs, 0, 8);

    // merge the two code-half candidates (half0 wins ties: lower idx)
    float mk, mi;
    if (k1 < k0) { mk = k1; mi = i1; }
    else         { mk = k0; mi = i0; }
    if (seg == 0) out_ind[n] = mi;

    float dmin = x2 + mk;
    float scale = sqrtf(fmaxf(dmin, 0.f)) / fmaxf(sqrtf(norm2), 1e-9f);

    float part = 0.f;
    #pragma unroll
    for (int i = 0; i < 8; ++i) {
        float q = zv[i] + nv[i] * scale;
        part += q;
        zq[row * 65 + seg * 8 + i] = q;
    }
    // full-warp shuffle reduce of part (warp w covers rows 4w..4w+3)
    #pragma unroll
    for (int d = 16; d > 0; d >>= 1)
        part += __shfl_down_sync(0xffffffffu, part, d);
    if ((t & 31) == 0) wred[t >> 5] = part;
    __syncthreads();

    // fixed-order chunk sums (warps 0-3 = rows 0-15, warps 4-7 = rows 16-31)
    if (t == 0) {
        float sv = ((wred[0] + wred[1]) + wred[2]) + wred[3];
        unsigned long long q =
            (unsigned long long)__double2ll_rn((double)sv * (double)sv * 4194304.0);
        atomicAdd(&g_lacc, q);
    }
    if (t == 128) {
        float sv = ((wred[4] + wred[5]) + wred[6]) + wred[7];
        unsigned long long q =
            (unsigned long long)__double2ll_rn((double)sv * (double)sv * 4194304.0);
        atomicAdd(&g_lacc, q);
    }

    // write out transposed: out[b*65536 + dd*1024 + p*32 + r]
    {
        int dd = t >> 2;
        int rg = t & 3;
        float4 o0, o1;
        o0.x = zq[(rg * 8 + 0) * 65 + dd];
        o0.y = zq[(rg * 8 + 1) * 65 + dd];
        o0.z = zq[(rg * 8 + 2) * 65 + dd];
        o0.w = zq[(rg * 8 + 3) * 65 + dd];
        o1.x = zq[(rg * 8 + 4) * 65 + dd];
        o1.y = zq[(rg * 8 + 5) * 65 + dd];
        o1.z = zq[(rg * 8 + 6) * 65 + dd];
        o1.w = zq[(rg * 8 + 7) * 65 + dd];
        float* op = out + (size_t)b * 65536 + dd * 1024 + p * 32 + rg * 8;
        *(float4*)op = o0;
        *(float4*)(op + 4) = o1;
    }

    // completion protocol
    __syncthreads();
    if (t == 0) {
        __threadfence();
        int v = atomicAdd(&g_ctr, 1);
        if (v == (int)gridDim.x - 1) {
            unsigned long long tot = atomicAdd(&g_lacc, 0ull);
            *out_loss = (float)((double)tot * (1.0 / 4194304.0) * (1.0 / 33554432.0));
            g_lacc = 0ull;   // reset for next graph replay
            g_ctr = 0;
            g_pk = 0;        // reset pack counter for next replay
        }
    }
}

// ---------------------------------------------------------------------------
extern "C" void kernel_launch(void* const* d_in, const int* in_sizes, int n_in,
                              void* d_out, int out_size) {
    const float* z     = (const float*)d_in[0];
    const float* cb    = (const float*)d_in[1];
    const float* noise = (const float*)d_in[2];
    float* out      = (float*)d_out;
    float* out_loss = out + ZQ_ELEMS;
    float* out_ind  = out + ZQ_ELEMS + 1;

    cudaFuncSetAttribute(gemm_argmin_kernel,
                         cudaFuncAttributeMaxDynamicSharedMemorySize, GEMM_SMEM);

    gemm_argmin_kernel<<<148, 512, GEMM_SMEM>>>(z, cb);
    zq_kernel<<<1024, 256>>>(z, noise, out, out_ind, out_loss);
}